// round 10
// baseline (speedup 1.0000x reference)
#include <cuda_runtime.h>
#include <cuda_fp16.h>

// out[i, :] = sum_k ppr_scores[i,k] * x[ppr_idx[i,k], :]
// N=100000, K=32, D=128 (fp32 in/out, 1e-3 rel-err budget).
// Two-pass: (1) convert x -> fp16 scratch (~12us, HBM floor);
// (2) gather 256B fp16 rows with half-warp row pairing, fp32 accumulate.
//
// R10: the gather is issue/FMA-bound (issue 66%, fma 48% in R9). Replace
// the 2x scalar FFMA per half2 with one packed fma.rn.f32x2 (FFMA2 —
// ptxas never emits it from C++). Accumulators live as 4x packed f32x2
// in 64-bit regs; scores broadcast as packed pairs. Memory path unchanged.

#define KNEIGH 32
#define DFEAT  128
#define NMAX   100000

// fp16 copy of x: 100000 * 128 * 2B = 25.6 MB (L2-resident).
__device__ __align__(16) static __half g_xh[(size_t)NMAX * DFEAT];

// ---- packed f32x2 helpers (sm_103a FFMA2 path) ----
__device__ __forceinline__ unsigned long long pack_f32x2(float lo, float hi) {
    unsigned long long r;
    asm("mov.b64 %0, {%1, %2};" : "=l"(r) : "f"(lo), "f"(hi));
    return r;
}
__device__ __forceinline__ void unpack_f32x2(unsigned long long v, float& lo, float& hi) {
    asm("mov.b64 {%0, %1}, %2;" : "=f"(lo), "=f"(hi) : "l"(v));
}
__device__ __forceinline__ void ffma2(unsigned long long& acc,
                                      unsigned long long a,
                                      unsigned long long b) {
    asm("fma.rn.f32x2 %0, %1, %2, %0;" : "+l"(acc) : "l"(a), "l"(b));
}
__device__ __forceinline__ unsigned long long h2_to_f32x2(unsigned h2bits) {
    const float2 f = __half22float2(*reinterpret_cast<const __half2*>(&h2bits));
    return pack_f32x2(f.x, f.y);
}

// ---------------- pass 1: fp32 -> fp16 convert ----------------
__global__ __launch_bounds__(256) void cvt_kernel(
    const float4* __restrict__ x, int n8)
{
    const int i = blockIdx.x * blockDim.x + threadIdx.x;
    if (i >= n8) return;

    const float4 a = x[2 * i];
    const float4 b = x[2 * i + 1];

    __half2 h0 = __floats2half2_rn(a.x, a.y);
    __half2 h1 = __floats2half2_rn(a.z, a.w);
    __half2 h2 = __floats2half2_rn(b.x, b.y);
    __half2 h3 = __floats2half2_rn(b.z, b.w);

    uint4 p;
    p.x = *reinterpret_cast<unsigned*>(&h0);
    p.y = *reinterpret_cast<unsigned*>(&h1);
    p.z = *reinterpret_cast<unsigned*>(&h2);
    p.w = *reinterpret_cast<unsigned*>(&h3);
    reinterpret_cast<uint4*>(g_xh)[i] = p;
}

// ---------------- pass 2: gather-reduce ----------------
// One warp per output row. Half-warp row pairing: one LDG.128 covers two
// neighbor rows (lanes 0-15 -> row 2u, lanes 16-31 -> row 2u+1; uint4 = 8
// features/lane). Even/odd-k partials folded by shfl_xor(16) at the end.
__global__ __launch_bounds__(256) void ppr_gather_kernel(
    const int*   __restrict__ idx,    // [N, 32]
    const float* __restrict__ sc,     // [N, 32]
    float4*      __restrict__ out,    // [N, 32] float4
    int n)
{
    const int warp = (blockIdx.x * blockDim.x + threadIdx.x) >> 5;
    const int lane = threadIdx.x & 31;
    if (warp >= n) return;

    const int half_id = lane >> 4;        // 0: even-k rows, 1: odd-k rows
    const int fbase16 = lane & 15;        // 16B-chunk index within a row

    const int   my_j = idx[warp * KNEIGH + lane];
    const float my_s = sc[warp * KNEIGH + lane];

    unsigned long long acc01 = 0ull, acc23 = 0ull,
                       acc45 = 0ull, acc67 = 0ull;

    #pragma unroll
    for (int i = 0; i < KNEIGH / 2; i += 2) {
        const int   jA = __shfl_sync(0xffffffffu, my_j, 2 * i + half_id);
        const float sA = __shfl_sync(0xffffffffu, my_s, 2 * i + half_id);
        const int   jB = __shfl_sync(0xffffffffu, my_j, 2 * i + 2 + half_id);
        const float sB = __shfl_sync(0xffffffffu, my_s, 2 * i + 2 + half_id);

        const uint4 vA = reinterpret_cast<const uint4*>(
                             g_xh + (size_t)jA * DFEAT)[fbase16];
        const uint4 vB = reinterpret_cast<const uint4*>(
                             g_xh + (size_t)jB * DFEAT)[fbase16];

        const unsigned long long sA2 = pack_f32x2(sA, sA);
        const unsigned long long sB2 = pack_f32x2(sB, sB);

        ffma2(acc01, h2_to_f32x2(vA.x), sA2);
        ffma2(acc23, h2_to_f32x2(vA.y), sA2);
        ffma2(acc45, h2_to_f32x2(vA.z), sA2);
        ffma2(acc67, h2_to_f32x2(vA.w), sA2);

        ffma2(acc01, h2_to_f32x2(vB.x), sB2);
        ffma2(acc23, h2_to_f32x2(vB.y), sB2);
        ffma2(acc45, h2_to_f32x2(vB.z), sB2);
        ffma2(acc67, h2_to_f32x2(vB.w), sB2);
    }

    float a0, a1, a2, a3, a4, a5, a6, a7;
    unpack_f32x2(acc01, a0, a1);
    unpack_f32x2(acc23, a2, a3);
    unpack_f32x2(acc45, a4, a5);
    unpack_f32x2(acc67, a6, a7);

    // Fold even-k (lanes 0-15) and odd-k (lanes 16-31) partial sums.
    a0 += __shfl_xor_sync(0xffffffffu, a0, 16);
    a1 += __shfl_xor_sync(0xffffffffu, a1, 16);
    a2 += __shfl_xor_sync(0xffffffffu, a2, 16);
    a3 += __shfl_xor_sync(0xffffffffu, a3, 16);
    a4 += __shfl_xor_sync(0xffffffffu, a4, 16);
    a5 += __shfl_xor_sync(0xffffffffu, a5, 16);
    a6 += __shfl_xor_sync(0xffffffffu, a6, 16);
    a7 += __shfl_xor_sync(0xffffffffu, a7, 16);

    const float4 r = half_id ? make_float4(a4, a5, a6, a7)
                             : make_float4(a0, a1, a2, a3);
    out[warp * (DFEAT / 4) + fbase16 * 2 + half_id] = r;
}

extern "C" void kernel_launch(void* const* d_in, const int* in_sizes, int n_in,
                              void* d_out, int out_size)
{
    const float4* x   = (const float4*)d_in[0];   // [N, D] fp32
    const int*    idx = (const int*)d_in[1];      // [N, K] int32
    const float*  sc  = (const float*)d_in[2];    // [N, K] fp32
    float4*       out = (float4*)d_out;           // [N, D] fp32

    const int n  = in_sizes[1] / KNEIGH;          // N rows
    const int n8 = in_sizes[0] / 8;               // convert units (8 floats)

    cvt_kernel<<<(n8 + 255) / 256, 256>>>(x, n8);

    const int warps_per_block = 8;                // 256 threads
    const int blocks = (n + warps_per_block - 1) / warps_per_block;
    ppr_gather_kernel<<<blocks, warps_per_block * 32>>>(idx, sc, out, n);
}